// round 16
// baseline (speedup 1.0000x reference)
#include <cuda_runtime.h>
#include <cuda_fp16.h>
#include <stdint.h>

#define EE     100000
#define DIN    192
#define KNB    8

// ---------------- scratch (device globals) ----------------
__device__ float g_qkv[EE * DIN];   // [E,192] = [q|k|v]
__device__ float g_ef1[EE * 64];    // [E,64] layer-1 out

// ---------------- helpers ----------------
__device__ __forceinline__ uint32_t f2h2(float a, float b) {
    __half2 h = __floats2half2_rn(a, b);
    return *reinterpret_cast<uint32_t*>(&h);
}
__device__ __forceinline__ void mma16(float* c, const uint32_t* a, uint32_t b0, uint32_t b1) {
    asm volatile("mma.sync.aligned.m16n8k16.row.col.f32.f16.f16.f32 "
        "{%0,%1,%2,%3}, {%4,%5,%6,%7}, {%8,%9}, {%0,%1,%2,%3};"
        : "+f"(c[0]), "+f"(c[1]), "+f"(c[2]), "+f"(c[3])
        : "r"(a[0]), "r"(a[1]), "r"(a[2]), "r"(a[3]), "r"(b0), "r"(b1));
}
__device__ __forceinline__ void ldsm4(uint32_t* f, uint32_t addr) {
    asm volatile("ldmatrix.sync.aligned.m8n8.x4.shared.b16 {%0,%1,%2,%3}, [%4];"
        : "=r"(f[0]), "=r"(f[1]), "=r"(f[2]), "=r"(f[3]) : "r"(addr));
}

// ---------------- QKV kernel smem geometry (fp16, BN=192 single-pass) ----------------
#define B16_STRIDE 200                   // 200 % 32 == 8 -> b-frag banks 8*t4+g distinct
#define B16_WORDS  (96 * B16_STRIDE)     // 19200
#define A16_STRIDE 20
#define A16_WORDS  (128 * A16_STRIDE)    // 2560
#define QKV_SMEM_BYTES ((B16_WORDS + 2 * A16_WORDS) * 4)   // 97280

// ---------------- fused attn+wo smem geometry (fp16 GEMM, r14 proven) ----------------
#define FST16      36                    // u32 stride; 36 % 32 == 4 -> banks distinct
#define FA16_WORDS (128 * FST16)         // 4608
#define FB16_WORDS (64 * FST16)          // 2304
#define FUSED_SMEM_BYTES ((FA16_WORDS + FB16_WORDS) * 4)  // 27648

// ======================================================================
// Fused QKV GEMM, fp16, single pass, r4 load-then-compute schedule.
// BM=128, BN=192, K=192 (B full-resident); 8 warps 2M x 4N, warp tile 64x48.
// ======================================================================
__global__ __launch_bounds__(256, 1) void qkv_mma_kernel(
    const float* __restrict__ ef, const float* __restrict__ nf,
    const int* __restrict__ ei,
    const float* __restrict__ wq, const float* __restrict__ wk, const float* __restrict__ wv,
    int use_ef1)
{
    extern __shared__ uint32_t smem[];
    uint32_t* Bs = smem;                   // [96][200]
    uint32_t* As = smem + B16_WORDS;       // [2][128*20]

    const int tid = threadIdx.x;
    const int m0  = blockIdx.x * 128;
    const float* efsrc = use_ef1 ? (const float*)g_ef1 : ef;

    const int r   = tid & 127;
    const int sel = tid >> 7;
    const int e   = m0 + r;
    const bool valid = (e < EE);
    int si = 0, di = 0;
    if (valid) { si = ei[e]; di = ei[EE + e]; }

    const int wid = tid >> 5, lane = tid & 31;
    const int wm = (wid & 1) * 64, wn = (wid >> 1) * 48;
    const int g = lane >> 2, t4 = lane & 3;
    const int j8 = lane & 7, grp = lane >> 3;

    // ---- B preload: [k2][n] fp16 pairs; coalesced reads, conflict-free uint4 writes ----
    #pragma unroll
    for (int i = 0; i < 18; i++) {                // 96 k2 x 48 n4-groups = 4608 items
        int item = i * 256 + tid;
        int n4 = (item % 48) * 4;
        int k2 = item / 48;
        const float* W = (n4 < 64) ? wq : (n4 < 128) ? wk : wv;
        int wcol = n4 & 63;
        float4 lo = *reinterpret_cast<const float4*>(W + (size_t)(2 * k2) * 64 + wcol);
        float4 hi = *reinterpret_cast<const float4*>(W + (size_t)(2 * k2 + 1) * 64 + wcol);
        *reinterpret_cast<uint4*>(&Bs[k2 * B16_STRIDE + n4]) =
            make_uint4(f2h2(lo.x, hi.x), f2h2(lo.y, hi.y), f2h2(lo.z, hi.z), f2h2(lo.w, hi.w));
    }

    // ---- ldmatrix A addresses ----
    const uint32_t As_b = (uint32_t)__cvta_generic_to_shared(As);
    uint32_t aAddr[4];
    #pragma unroll
    for (int mt = 0; mt < 4; mt++) {
        int row = wm + mt * 16 + (grp & 1) * 8 + j8;
        int col = (grp >> 1) * 4;
        aAddr[mt] = As_b + (row * A16_STRIDE + col) * 4;
    }

    float acc[4][6][4];
    #pragma unroll
    for (int i = 0; i < 4; i++)
        #pragma unroll
        for (int j = 0; j < 6; j++)
            #pragma unroll
            for (int q = 0; q < 4; q++) acc[i][j][q] = 0.f;

    uint32_t av16[8];
    auto ldg_tile = [&](int it) {
        const int k0 = it * 32;
        if (valid) {
            const int reg = k0 >> 6;
            const float* base = (reg == 0) ? efsrc + (size_t)e * 64
                              : (reg == 1) ? nf + (size_t)si * 64
                                           : nf + (size_t)di * 64;
            base += (k0 & 32) + sel * 16;
            #pragma unroll
            for (int c = 0; c < 4; c++) {
                float4 v = *reinterpret_cast<const float4*>(base + c * 4);
                av16[c * 2 + 0] = f2h2(v.x, v.y);
                av16[c * 2 + 1] = f2h2(v.z, v.w);
            }
        } else {
            #pragma unroll
            for (int c = 0; c < 8; c++) av16[c] = 0u;
        }
    };
    auto sts_tile = [&](int b) {
        uint32_t* Aw = As + b * A16_WORDS + r * A16_STRIDE + sel * 8;
        *reinterpret_cast<uint4*>(Aw)     = make_uint4(av16[0], av16[1], av16[2], av16[3]);
        *reinterpret_cast<uint4*>(Aw + 4) = make_uint4(av16[4], av16[5], av16[6], av16[7]);
    };

    const uint32_t* Bwp = Bs + wn + g;

    const int NIT = DIN / 32;   // 6
    ldg_tile(0);
    sts_tile(0);
    ldg_tile(1);
    __syncthreads();

    for (int i = 0; i < NIT; i++) {
        const int cur = i & 1;
        const uint32_t aOff = cur * (A16_WORDS * 4);
        #pragma unroll
        for (int step = 0; step < 2; step++) {
            const int k2 = i * 16 + step * 8 + t4;
            // hoist ALL fragment loads before any mma (r4 schedule)
            uint32_t af[4][4];
            #pragma unroll
            for (int mt = 0; mt < 4; mt++)
                ldsm4(af[mt], aAddr[mt] + aOff + step * 32);
            uint32_t b0[6], b1[6];
            #pragma unroll
            for (int nt = 0; nt < 6; nt++) {
                b0[nt] = Bwp[k2 * B16_STRIDE + nt * 8];
                b1[nt] = Bwp[(k2 + 4) * B16_STRIDE + nt * 8];
            }
            #pragma unroll
            for (int mt = 0; mt < 4; mt++)
                #pragma unroll
                for (int nt = 0; nt < 6; nt++)
                    mma16(acc[mt][nt], af[mt], b0[nt], b1[nt]);
        }
        if (i + 1 < NIT) {
            sts_tile(cur ^ 1);
            if (i + 2 < NIT) ldg_tile(i + 2);
            __syncthreads();
        }
    }

    // ---- epilogue ----
    #pragma unroll
    for (int mt = 0; mt < 4; mt++) {
        const int row = m0 + wm + mt * 16 + g;
        #pragma unroll
        for (int nt = 0; nt < 6; nt++) {
            const int col = wn + nt * 8 + t4 * 2;
            if (row < EE)
                *reinterpret_cast<float2*>(g_qkv + (size_t)row * DIN + col) =
                    make_float2(acc[mt][nt][0], acc[mt][nt][1]);
            if (row + 8 < EE)
                *reinterpret_cast<float2*>(g_qkv + (size_t)(row + 8) * DIN + col) =
                    make_float2(acc[mt][nt][2], acc[mt][nt][3]);
        }
    }
}

// ======================================================================
// FUSED attention + Wo GEMM + residual — fp16 GEMM tiles (r14/r15 proven, 50.1us).
// ======================================================================
__global__ __launch_bounds__(256, 3) void attn_wo_kernel(
    const float* __restrict__ Wo,
    const int* __restrict__ adj_src,
    const float* __restrict__ ef_ext, float* __restrict__ out_ext,
    int use_ef1_in, int write_ef1)
{
    extern __shared__ uint32_t smem[];
    uint32_t* As = smem;                   // [128][36] u32 = fp16 pairs along k
    uint32_t* Bs = smem + FA16_WORDS;      // [64][36]  Wo [n][k2]

    const int tid = threadIdx.x;
    const int m0  = blockIdx.x * 128;
    const float* ef_in = use_ef1_in ? (const float*)g_ef1 : ef_ext;
    float* out = write_ef1 ? (float*)g_ef1 : out_ext;

    const int wid = tid >> 5, lane = tid & 31;

    // ---- Wo preload -> Bs[n][k2] fp16 pairs ----
    #pragma unroll
    for (int i = 0; i < 2; i++) {
        int item = i * 256 + tid;
        int k2 = item & 31;
        int n4 = (item >> 5) * 4;
        float4 lo = *reinterpret_cast<const float4*>(Wo + (size_t)(2 * k2) * 64 + n4);
        float4 hi = *reinterpret_cast<const float4*>(Wo + (size_t)(2 * k2 + 1) * 64 + n4);
        Bs[(n4 + 0) * FST16 + k2] = f2h2(lo.x, hi.x);
        Bs[(n4 + 1) * FST16 + k2] = f2h2(lo.y, hi.y);
        Bs[(n4 + 2) * FST16 + k2] = f2h2(lo.z, hi.z);
        Bs[(n4 + 3) * FST16 + k2] = f2h2(lo.w, hi.w);
    }

    // ---- phase 1: attention into As (fp32 math, fp16 store) ----
    {
        const int sub = lane >> 4, l16 = lane & 15;
        #pragma unroll
        for (int iter = 0; iter < 8; iter++) {
            const int el = iter * 16 + wid * 2 + sub;
            const int e = m0 + el;
            const int ec = (e < EE) ? e : (EE - 1);   // clamp: keeps shuffles convergent

            const float* qrow = g_qkv + (size_t)ec * DIN;
            float4 q = *reinterpret_cast<const float4*>(qrow + 4 * l16);

            int nb[KNB];
            const int base = ec * KNB;
            #pragma unroll
            for (int j = 0; j < KNB; j++) nb[j] = adj_src[base + j];

            float sj[KNB];
            #pragma unroll
            for (int c = 0; c < 2; c++) {
                float4 kk[4];
                #pragma unroll
                for (int j = 0; j < 4; j++)
                    kk[j] = *reinterpret_cast<const float4*>(
                        g_qkv + (size_t)nb[c * 4 + j] * DIN + 64 + 4 * l16);
                #pragma unroll
                for (int j = 0; j < 4; j++) {
                    float p = q.x * kk[j].x + q.y * kk[j].y + q.z * kk[j].z + q.w * kk[j].w;
                    p += __shfl_xor_sync(0xffffffffu, p, 1);
                    p += __shfl_xor_sync(0xffffffffu, p, 2);   // head-local (4 lanes)
                    sj[c * 4 + j] = p * 0.25f;                  // 1/sqrt(16)
                }
            }

            float m = sj[0];
            #pragma unroll
            for (int j = 1; j < KNB; j++) m = fmaxf(m, sj[j]);

            float denom = 0.f;
            float4 a = make_float4(0.f, 0.f, 0.f, 0.f);
            #pragma unroll
            for (int c = 0; c < 2; c++) {
                float4 vv[4];
                #pragma unroll
                for (int j = 0; j < 4; j++)
                    vv[j] = *reinterpret_cast<const float4*>(
                        g_qkv + (size_t)nb[c * 4 + j] * DIN + 128 + 4 * l16);
                #pragma unroll
                for (int j = 0; j < 4; j++) {
                    float w = __expf(sj[c * 4 + j] - m);
                    denom += w;
                    a.x += w * vv[j].x; a.y += w * vv[j].y;
                    a.z += w * vv[j].z; a.w += w * vv[j].w;
                }
            }
            float inv = 1.0f / denom;
            As[el * FST16 + 2 * l16 + 0] = f2h2(a.x * inv, a.y * inv);
            As[el * FST16 + 2 * l16 + 1] = f2h2(a.z * inv, a.w * inv);
        }
    }
    __syncthreads();

    // ---- phase 2: fp16 GEMM 128x64x64 + residual (8 warps 4M x 2N) ----
    const int wm = (wid & 3) * 32, wn = (wid >> 2) * 32;
    const int g = lane >> 2, t4 = lane & 3;
    const int j8 = lane & 7, grp = lane >> 3;

    const uint32_t As_b = (uint32_t)__cvta_generic_to_shared(As);
    uint32_t aAddr[2];
    #pragma unroll
    for (int mt = 0; mt < 2; mt++) {
        int row = wm + mt * 16 + (grp & 1) * 8 + j8;
        int col = (grp >> 1) * 4;
        aAddr[mt] = As_b + (row * FST16 + col) * 4;
    }
    const uint32_t* Bwp = Bs + (wn + g) * FST16;

    float acc[2][4][4];
    #pragma unroll
    for (int i = 0; i < 2; i++)
        #pragma unroll
        for (int j = 0; j < 4; j++)
            #pragma unroll
            for (int q = 0; q < 4; q++) acc[i][j][q] = 0.f;

    #pragma unroll
    for (int step = 0; step < 4; step++) {
        const int k2 = step * 8 + t4;
        uint32_t af[2][4];
        ldsm4(af[0], aAddr[0] + step * 32);
        ldsm4(af[1], aAddr[1] + step * 32);
        uint32_t b0[4], b1[4];
        #pragma unroll
        for (int nt = 0; nt < 4; nt++) {
            b0[nt] = Bwp[nt * 8 * FST16 + k2];
            b1[nt] = Bwp[nt * 8 * FST16 + k2 + 4];
        }
        #pragma unroll
        for (int mt = 0; mt < 2; mt++)
            #pragma unroll
            for (int nt = 0; nt < 4; nt++)
                mma16(acc[mt][nt], af[mt], b0[nt], b1[nt]);
    }

    // ---- epilogue with residual ----
    #pragma unroll
    for (int mt = 0; mt < 2; mt++) {
        const int row = m0 + wm + mt * 16 + g;
        #pragma unroll
        for (int nt = 0; nt < 4; nt++) {
            const int col = wn + nt * 8 + t4 * 2;
            if (row < EE) {
                float2 rr = *reinterpret_cast<const float2*>(ef_in + (size_t)row * 64 + col);
                *reinterpret_cast<float2*>(out + (size_t)row * 64 + col) =
                    make_float2(rr.x + acc[mt][nt][0], rr.y + acc[mt][nt][1]);
            }
            if (row + 8 < EE) {
                float2 rr = *reinterpret_cast<const float2*>(ef_in + (size_t)(row + 8) * 64 + col);
                *reinterpret_cast<float2*>(out + (size_t)(row + 8) * 64 + col) =
                    make_float2(rr.x + acc[mt][nt][2], rr.y + acc[mt][nt][3]);
            }
        }
    }
}

// ---------------- launch ----------------
extern "C" void kernel_launch(void* const* d_in, const int* in_sizes, int n_in,
                              void* d_out, int out_size) {
    const float* nf      = (const float*)d_in[0];
    const float* ef      = (const float*)d_in[1];
    const int*   ei      = (const int*)d_in[2];
    const int*   adj_src = (const int*)d_in[4];
    const float* l1_Wq = (const float*)d_in[6];
    const float* l1_Wk = (const float*)d_in[7];
    const float* l1_Wv = (const float*)d_in[8];
    const float* l1_Wo = (const float*)d_in[9];
    const float* l2_Wq = (const float*)d_in[10];
    const float* l2_Wk = (const float*)d_in[11];
    const float* l2_Wv = (const float*)d_in[12];
    const float* l2_Wo = (const float*)d_in[13];
    float* out = (float*)d_out;

    static int attr_done = 0;
    if (!attr_done) {
        cudaFuncSetAttribute(qkv_mma_kernel, cudaFuncAttributeMaxDynamicSharedMemorySize, QKV_SMEM_BYTES);
        cudaFuncSetAttribute(attn_wo_kernel, cudaFuncAttributeMaxDynamicSharedMemorySize, FUSED_SMEM_BYTES);
        attr_done = 1;
    }

    const int gq = (EE + 127) / 128;   // 782
    const int gf = (EE + 127) / 128;   // 782

    // layer 1
    qkv_mma_kernel<<<gq, 256, QKV_SMEM_BYTES>>>(ef, nf, ei, l1_Wq, l1_Wk, l1_Wv, 0);
    attn_wo_kernel<<<gf, 256, FUSED_SMEM_BYTES>>>(l1_Wo, adj_src, ef, nullptr, 0, 1);

    // layer 2
    qkv_mma_kernel<<<gq, 256, QKV_SMEM_BYTES>>>(ef, nf, ei, l2_Wq, l2_Wk, l2_Wv, 1);
    attn_wo_kernel<<<gf, 256, FUSED_SMEM_BYTES>>>(l2_Wo, adj_src, nullptr, out, 1, 0);
}

// round 17
// speedup vs baseline: 1.1131x; 1.1131x over previous
#include <cuda_runtime.h>
#include <cuda_fp16.h>
#include <stdint.h>

#define EE     100000
#define DIN    192
#define KNB    8

// ---------------- scratch (device globals) ----------------
__device__ float g_qkv[EE * DIN];   // [E,192] = [q|k|v]
__device__ float g_ef1[EE * 64];    // [E,64] layer-1 out

// ---------------- helpers ----------------
__device__ __forceinline__ uint32_t f2tf(float x) {
    uint32_t u; asm("cvt.rna.tf32.f32 %0, %1;" : "=r"(u) : "f"(x)); return u;
}
__device__ __forceinline__ uint32_t f2h2(float a, float b) {
    __half2 h = __floats2half2_rn(a, b);
    return *reinterpret_cast<uint32_t*>(&h);
}
__device__ __forceinline__ void mma8(float* c, const uint32_t* a, uint32_t b0, uint32_t b1) {
    asm volatile("mma.sync.aligned.m16n8k8.row.col.f32.tf32.tf32.f32 "
        "{%0,%1,%2,%3}, {%4,%5,%6,%7}, {%8,%9}, {%0,%1,%2,%3};"
        : "+f"(c[0]), "+f"(c[1]), "+f"(c[2]), "+f"(c[3])
        : "r"(a[0]), "r"(a[1]), "r"(a[2]), "r"(a[3]), "r"(b0), "r"(b1));
}
__device__ __forceinline__ void mma16(float* c, const uint32_t* a, uint32_t b0, uint32_t b1) {
    asm volatile("mma.sync.aligned.m16n8k16.row.col.f32.f16.f16.f32 "
        "{%0,%1,%2,%3}, {%4,%5,%6,%7}, {%8,%9}, {%0,%1,%2,%3};"
        : "+f"(c[0]), "+f"(c[1]), "+f"(c[2]), "+f"(c[3])
        : "r"(a[0]), "r"(a[1]), "r"(a[2]), "r"(a[3]), "r"(b0), "r"(b1));
}
__device__ __forceinline__ void ldsm4(uint32_t* f, uint32_t addr) {
    asm volatile("ldmatrix.sync.aligned.m8n8.x4.shared.b16 {%0,%1,%2,%3}, [%4];"
        : "=r"(f[0]), "=r"(f[1]), "=r"(f[2]), "=r"(f[3]) : "r"(addr));
}

// ---------------- QKV kernel smem geometry (tf32, r4/r13 proven) ----------------
#define BSTRIDE    200
#define B_WORDS_F  (192 * BSTRIDE)      // 38400
#define A_WORDS    (128 * 36)           // 4608
#define QKV_SMEM_BYTES ((B_WORDS_F + 2 * A_WORDS) * 4)

// ---------------- fused attn+wo smem geometry (fp16 GEMM, r14-16 proven) ----------------
#define FST16      36                    // u32 stride; 36 % 32 == 4 -> banks distinct
#define FA16_WORDS (128 * FST16)         // 4608
#define FB16_WORDS (64 * FST16)          // 2304
#define FUSED_SMEM_BYTES ((FA16_WORDS + FB16_WORDS) * 4)  // 27648

// ======================================================================
// Fused QKV GEMM (tf32, r4/r13 proven, 76.8us): qkv = concat(...) @ [Wq|Wk|Wv]
// BM=128, BN=192, BK=32; 8 warps as 2M x 4N, warp tile 64x48.
// ======================================================================
__global__ __launch_bounds__(256, 1) void qkv_mma_kernel(
    const float* __restrict__ ef, const float* __restrict__ nf,
    const int* __restrict__ ei,
    const float* __restrict__ wq, const float* __restrict__ wk, const float* __restrict__ wv,
    int use_ef1)
{
    extern __shared__ uint32_t smem[];
    uint32_t* Bs = smem;                 // [192][200]
    uint32_t* As = smem + B_WORDS_F;     // [2][128*36]

    const int tid = threadIdx.x;
    const int m0  = blockIdx.x * 128;
    const float* efsrc = use_ef1 ? (const float*)g_ef1 : ef;

    const int r  = tid >> 1;
    const int e  = m0 + r;
    const int kb = (tid & 1) * 16;
    const bool valid = (e < EE);
    int si = 0, di = 0;
    if (valid) { si = ei[e]; di = ei[EE + e]; }

    const int wid = tid >> 5, lane = tid & 31;
    const int wm = (wid & 1) * 64, wn = (wid >> 1) * 48;
    const int g = lane >> 2, t4 = lane & 3;
    const int j8 = lane & 7, grp = lane >> 3;

    // ---- preload full B into smem (tf32) ----
    {
        #pragma unroll
        for (int w = 0; w < 3; w++) {
            const float* W = (w == 0) ? wq : (w == 1) ? wk : wv;
            #pragma unroll
            for (int j = 0; j < 12; j++) {
                int f = j * 256 + tid;
                int k = f >> 4;
                int n4 = (f & 15) * 4;
                float4 v = *reinterpret_cast<const float4*>(W + (size_t)k * 64 + n4);
                uint32_t* dst = Bs + k * BSTRIDE + w * 64 + n4;
                dst[0] = f2tf(v.x); dst[1] = f2tf(v.y);
                dst[2] = f2tf(v.z); dst[3] = f2tf(v.w);
            }
        }
    }

    const uint32_t As_b = (uint32_t)__cvta_generic_to_shared(As);
    uint32_t aAddr[4];
    #pragma unroll
    for (int mt = 0; mt < 4; mt++) {
        int row = wm + mt * 16 + (grp & 1) * 8 + j8;
        int col = (grp >> 1) * 4;
        aAddr[mt] = As_b + (row * 36 + col) * 4;
    }

    float acc[4][6][4];
    #pragma unroll
    for (int i = 0; i < 4; i++)
        #pragma unroll
        for (int j = 0; j < 6; j++)
            #pragma unroll
            for (int q = 0; q < 4; q++) acc[i][j][q] = 0.f;

    float4 av[4];
    auto ldg_tile = [&](int it) {
        const int k0 = it * 32;
        if (valid) {
            const int reg = k0 >> 6;
            const float* base = (reg == 0) ? efsrc + (size_t)e * 64
                              : (reg == 1) ? nf + (size_t)si * 64
                                           : nf + (size_t)di * 64;
            const int cb = (k0 & 32) + kb;
            #pragma unroll
            for (int c = 0; c < 4; c++) av[c] = *reinterpret_cast<const float4*>(base + cb + c * 4);
        } else {
            #pragma unroll
            for (int c = 0; c < 4; c++) av[c] = make_float4(0.f, 0.f, 0.f, 0.f);
        }
    };
    auto sts_tile = [&](int b) {
        uint32_t* Aw = As + b * A_WORDS;
        #pragma unroll
        for (int c = 0; c < 4; c++) {
            uint4 u = make_uint4(f2tf(av[c].x), f2tf(av[c].y), f2tf(av[c].z), f2tf(av[c].w));
            *reinterpret_cast<uint4*>(&Aw[r * 36 + kb + c * 4]) = u;
        }
    };

    const uint32_t* Bwp = Bs + wn + g;

    const int NIT = DIN / 32;   // 6
    ldg_tile(0);
    sts_tile(0);
    ldg_tile(1);
    __syncthreads();

    for (int i = 0; i < NIT; i++) {
        const int cur = i & 1;
        const uint32_t aOff = cur * (A_WORDS * 4);
        #pragma unroll
        for (int ks = 0; ks < 4; ks++) {
            const int kg = i * 32 + ks * 8 + t4;
            uint32_t af[4][4];
            #pragma unroll
            for (int mt = 0; mt < 4; mt++) ldsm4(af[mt], aAddr[mt] + aOff + ks * 32);
            uint32_t b0[6], b1[6];
            #pragma unroll
            for (int nt = 0; nt < 6; nt++) {
                b0[nt] = Bwp[kg * BSTRIDE + nt * 8];
                b1[nt] = Bwp[(kg + 4) * BSTRIDE + nt * 8];
            }
            #pragma unroll
            for (int mt = 0; mt < 4; mt++)
                #pragma unroll
                for (int nt = 0; nt < 6; nt++)
                    mma8(acc[mt][nt], af[mt], b0[nt], b1[nt]);
        }
        if (i + 1 < NIT) {
            sts_tile(cur ^ 1);
            if (i + 2 < NIT) ldg_tile(i + 2);
            __syncthreads();
        }
    }

    #pragma unroll
    for (int mt = 0; mt < 4; mt++) {
        const int row = m0 + wm + mt * 16 + g;
        #pragma unroll
        for (int nt = 0; nt < 6; nt++) {
            const int col = wn + nt * 8 + t4 * 2;
            if (row < EE)
                *reinterpret_cast<float2*>(g_qkv + (size_t)row * DIN + col) =
                    make_float2(acc[mt][nt][0], acc[mt][nt][1]);
            if (row + 8 < EE)
                *reinterpret_cast<float2*>(g_qkv + (size_t)(row + 8) * DIN + col) =
                    make_float2(acc[mt][nt][2], acc[mt][nt][3]);
        }
    }
}

// ======================================================================
// FUSED attention + Wo GEMM + residual — fp16 GEMM tiles (r16 proven, 49.6us).
// ======================================================================
__global__ __launch_bounds__(256, 3) void attn_wo_kernel(
    const float* __restrict__ Wo,
    const int* __restrict__ adj_src,
    const float* __restrict__ ef_ext, float* __restrict__ out_ext,
    int use_ef1_in, int write_ef1)
{
    extern __shared__ uint32_t smem[];
    uint32_t* As = smem;                   // [128][36] u32 = fp16 pairs along k
    uint32_t* Bs = smem + FA16_WORDS;      // [64][36]  Wo [n][k2]

    const int tid = threadIdx.x;
    const int m0  = blockIdx.x * 128;
    const float* ef_in = use_ef1_in ? (const float*)g_ef1 : ef_ext;
    float* out = write_ef1 ? (float*)g_ef1 : out_ext;

    const int wid = tid >> 5, lane = tid & 31;

    // ---- Wo preload -> Bs[n][k2] fp16 pairs ----
    #pragma unroll
    for (int i = 0; i < 2; i++) {
        int item = i * 256 + tid;
        int k2 = item & 31;
        int n4 = (item >> 5) * 4;
        float4 lo = *reinterpret_cast<const float4*>(Wo + (size_t)(2 * k2) * 64 + n4);
        float4 hi = *reinterpret_cast<const float4*>(Wo + (size_t)(2 * k2 + 1) * 64 + n4);
        Bs[(n4 + 0) * FST16 + k2] = f2h2(lo.x, hi.x);
        Bs[(n4 + 1) * FST16 + k2] = f2h2(lo.y, hi.y);
        Bs[(n4 + 2) * FST16 + k2] = f2h2(lo.z, hi.z);
        Bs[(n4 + 3) * FST16 + k2] = f2h2(lo.w, hi.w);
    }

    // ---- phase 1: attention into As (fp32 math, fp16 store) ----
    {
        const int sub = lane >> 4, l16 = lane & 15;
        #pragma unroll
        for (int iter = 0; iter < 8; iter++) {
            const int el = iter * 16 + wid * 2 + sub;
            const int e = m0 + el;
            const int ec = (e < EE) ? e : (EE - 1);   // clamp: keeps shuffles convergent

            const float* qrow = g_qkv + (size_t)ec * DIN;
            float4 q = *reinterpret_cast<const float4*>(qrow + 4 * l16);

            int nb[KNB];
            const int base = ec * KNB;
            #pragma unroll
            for (int j = 0; j < KNB; j++) nb[j] = adj_src[base + j];

            float sj[KNB];
            #pragma unroll
            for (int c = 0; c < 2; c++) {
                float4 kk[4];
                #pragma unroll
                for (int j = 0; j < 4; j++)
                    kk[j] = *reinterpret_cast<const float4*>(
                        g_qkv + (size_t)nb[c * 4 + j] * DIN + 64 + 4 * l16);
                #pragma unroll
                for (int j = 0; j < 4; j++) {
                    float p = q.x * kk[j].x + q.y * kk[j].y + q.z * kk[j].z + q.w * kk[j].w;
                    p += __shfl_xor_sync(0xffffffffu, p, 1);
                    p += __shfl_xor_sync(0xffffffffu, p, 2);   // head-local (4 lanes)
                    sj[c * 4 + j] = p * 0.25f;                  // 1/sqrt(16)
                }
            }

            float m = sj[0];
            #pragma unroll
            for (int j = 1; j < KNB; j++) m = fmaxf(m, sj[j]);

            float denom = 0.f;
            float4 a = make_float4(0.f, 0.f, 0.f, 0.f);
            #pragma unroll
            for (int c = 0; c < 2; c++) {
                float4 vv[4];
                #pragma unroll
                for (int j = 0; j < 4; j++)
                    vv[j] = *reinterpret_cast<const float4*>(
                        g_qkv + (size_t)nb[c * 4 + j] * DIN + 128 + 4 * l16);
                #pragma unroll
                for (int j = 0; j < 4; j++) {
                    float w = __expf(sj[c * 4 + j] - m);
                    denom += w;
                    a.x += w * vv[j].x; a.y += w * vv[j].y;
                    a.z += w * vv[j].z; a.w += w * vv[j].w;
                }
            }
            float inv = 1.0f / denom;
            As[el * FST16 + 2 * l16 + 0] = f2h2(a.x * inv, a.y * inv);
            As[el * FST16 + 2 * l16 + 1] = f2h2(a.z * inv, a.w * inv);
        }
    }
    __syncthreads();

    // ---- phase 2: fp16 GEMM 128x64x64 + residual (8 warps 4M x 2N) ----
    const int wm = (wid & 3) * 32, wn = (wid >> 2) * 32;
    const int g = lane >> 2, t4 = lane & 3;
    const int j8 = lane & 7, grp = lane >> 3;

    const uint32_t As_b = (uint32_t)__cvta_generic_to_shared(As);
    uint32_t aAddr[2];
    #pragma unroll
    for (int mt = 0; mt < 2; mt++) {
        int row = wm + mt * 16 + (grp & 1) * 8 + j8;
        int col = (grp >> 1) * 4;
        aAddr[mt] = As_b + (row * FST16 + col) * 4;
    }
    const uint32_t* Bwp = Bs + (wn + g) * FST16;

    float acc[2][4][4];
    #pragma unroll
    for (int i = 0; i < 2; i++)
        #pragma unroll
        for (int j = 0; j < 4; j++)
            #pragma unroll
            for (int q = 0; q < 4; q++) acc[i][j][q] = 0.f;

    #pragma unroll
    for (int step = 0; step < 4; step++) {
        const int k2 = step * 8 + t4;
        uint32_t af[2][4];
        ldsm4(af[0], aAddr[0] + step * 32);
        ldsm4(af[1], aAddr[1] + step * 32);
        uint32_t b0[4], b1[4];
        #pragma unroll
        for (int nt = 0; nt < 4; nt++) {
            b0[nt] = Bwp[nt * 8 * FST16 + k2];
            b1[nt] = Bwp[nt * 8 * FST16 + k2 + 4];
        }
        #pragma unroll
        for (int mt = 0; mt < 2; mt++)
            #pragma unroll
            for (int nt = 0; nt < 4; nt++)
                mma16(acc[mt][nt], af[mt], b0[nt], b1[nt]);
    }

    // ---- epilogue with residual ----
    #pragma unroll
    for (int mt = 0; mt < 2; mt++) {
        const int row = m0 + wm + mt * 16 + g;
        #pragma unroll
        for (int nt = 0; nt < 4; nt++) {
            const int col = wn + nt * 8 + t4 * 2;
            if (row < EE) {
                float2 rr = *reinterpret_cast<const float2*>(ef_in + (size_t)row * 64 + col);
                *reinterpret_cast<float2*>(out + (size_t)row * 64 + col) =
                    make_float2(rr.x + acc[mt][nt][0], rr.y + acc[mt][nt][1]);
            }
            if (row + 8 < EE) {
                float2 rr = *reinterpret_cast<const float2*>(ef_in + (size_t)(row + 8) * 64 + col);
                *reinterpret_cast<float2*>(out + (size_t)(row + 8) * 64 + col) =
                    make_float2(rr.x + acc[mt][nt][2], rr.y + acc[mt][nt][3]);
            }
        }
    }
}

// ---------------- launch ----------------
extern "C" void kernel_launch(void* const* d_in, const int* in_sizes, int n_in,
                              void* d_out, int out_size) {
    const float* nf      = (const float*)d_in[0];
    const float* ef      = (const float*)d_in[1];
    const int*   ei      = (const int*)d_in[2];
    const int*   adj_src = (const int*)d_in[4];
    const float* l1_Wq = (const float*)d_in[6];
    const float* l1_Wk = (const float*)d_in[7];
    const float* l1_Wv = (const float*)d_in[8];
    const float* l1_Wo = (const float*)d_in[9];
    const float* l2_Wq = (const float*)d_in[10];
    const float* l2_Wk = (const float*)d_in[11];
    const float* l2_Wv = (const float*)d_in[12];
    const float* l2_Wo = (const float*)d_in[13];
    float* out = (float*)d_out;

    static int attr_done = 0;
    if (!attr_done) {
        cudaFuncSetAttribute(qkv_mma_kernel, cudaFuncAttributeMaxDynamicSharedMemorySize, QKV_SMEM_BYTES);
        cudaFuncSetAttribute(attn_wo_kernel, cudaFuncAttributeMaxDynamicSharedMemorySize, FUSED_SMEM_BYTES);
        attr_done = 1;
    }

    const int gq = (EE + 127) / 128;   // 782
    const int gf = (EE + 127) / 128;   // 782

    // layer 1
    qkv_mma_kernel<<<gq, 256, QKV_SMEM_BYTES>>>(ef, nf, ei, l1_Wq, l1_Wk, l1_Wv, 0);
    attn_wo_kernel<<<gf, 256, FUSED_SMEM_BYTES>>>(l1_Wo, adj_src, ef, nullptr, 0, 1);

    // layer 2
    qkv_mma_kernel<<<gq, 256, QKV_SMEM_BYTES>>>(ef, nf, ei, l2_Wq, l2_Wk, l2_Wv, 1);
    attn_wo_kernel<<<gf, 256, FUSED_SMEM_BYTES>>>(l2_Wo, adj_src, nullptr, out, 1, 0);
}